// round 1
// baseline (speedup 1.0000x reference)
#include <cuda_runtime.h>
#include <cuda_bf16.h>
#include <cstdint>

#define NUM_TAGS 48
#define SEQ_LEN  512
#define BATCH    1024
#define NT2      (NUM_TAGS/2)   // 24 packed f32x2 per column

__device__ float g_nll[BATCH];

// packed f32x2 helpers (Blackwell FFMA2 path — PTX only, ptxas won't auto-fuse)
__device__ __forceinline__ void fma2(uint64_t& d, uint64_t a, uint64_t b) {
    asm("fma.rn.f32x2 %0, %1, %2, %0;" : "+l"(d) : "l"(a), "l"(b));
}
__device__ __forceinline__ uint64_t add2(uint64_t a, uint64_t b) {
    uint64_t d;
    asm("add.rn.f32x2 %0, %1, %2;" : "=l"(d) : "l"(a), "l"(b));
    return d;
}
__device__ __forceinline__ uint64_t pack2(float lo, float hi) {
    uint64_t d;
    asm("mov.b64 %0, {%1, %2};" : "=l"(d) : "f"(lo), "f"(hi));
    return d;
}
__device__ __forceinline__ float lo2(uint64_t v) { return __uint_as_float((uint32_t)v); }
__device__ __forceinline__ float hi2(uint64_t v) { return __uint_as_float((uint32_t)(v >> 32)); }

__global__ __launch_bounds__(64)
void crf_forward_kernel(const float* __restrict__ emissions,
                        const float* __restrict__ transitions,
                        const int*   __restrict__ tags,
                        const int*   __restrict__ mask)
{
    const int b   = blockIdx.x;
    const int tid = threadIdx.x;

    __shared__ __align__(16) float wbuf[2][NUM_TAGS];  // ping-pong alphas (linear domain)
    __shared__ int   smask[SEQ_LEN];
    __shared__ float sred;
    __shared__ float rsh[64];

    const float* em_b   = emissions + (size_t)b * SEQ_LEN * NUM_TAGS;
    const int*   tags_b = tags + (size_t)b * SEQ_LEN;
    const int*   mask_b = mask + (size_t)b * SEQ_LEN;

    // preload mask into shared
    #pragma unroll
    for (int t = tid; t < SEQ_LEN; t += 64) smask[t] = mask_b[t];

    // Column j of E = exp(transitions) in registers, packed 2 rows per 64-bit reg.
    uint64_t Ecol[NT2];
    if (tid < NUM_TAGS) {
        #pragma unroll
        for (int i = 0; i < NUM_TAGS; i += 2) {
            float elo = __expf(transitions[(i    ) * NUM_TAGS + tid]);
            float ehi = __expf(transitions[(i + 1) * NUM_TAGS + tid]);
            Ecol[i >> 1] = pack2(elo, ehi);
        }
        wbuf[0][tid] = (tid == 0) ? 1.0f : 0.0f;   // alphas0: only tag 0 live
    }
    __syncthreads();

    // ---------------- forward recursion, linear domain with renorm every 8 ----
    float C = 0.0f;   // accumulated log-scale (identical in every thread)
    int   p = 0;
    float e_cur = (tid < NUM_TAGS) ? em_b[tid] : 0.0f;

    for (int t = 0; t < SEQ_LEN; t++) {
        float e_nxt = 0.0f;
        if (t + 1 < SEQ_LEN && tid < NUM_TAGS)
            e_nxt = em_b[(size_t)(t + 1) * NUM_TAGS + tid];

        if (tid < NUM_TAGS) {
            const uint64_t* wv = (const uint64_t*)(&wbuf[p][0]);
            uint64_t a0 = 0, a1 = 0, a2 = 0, a3 = 0;
            #pragma unroll
            for (int i = 0; i < NT2; i += 4) {
                fma2(a0, wv[i    ], Ecol[i    ]);
                fma2(a1, wv[i + 1], Ecol[i + 1]);
                fma2(a2, wv[i + 2], Ecol[i + 2]);
                fma2(a3, wv[i + 3], Ecol[i + 3]);
            }
            uint64_t s2 = add2(add2(a0, a1), add2(a2, a3));
            float nxt = (lo2(s2) + hi2(s2)) * __expf(e_cur);
            wbuf[1 - p][tid] = smask[t] ? nxt : wbuf[p][tid];
        }
        e_cur = e_nxt;
        __syncthreads();

        if ((t & 7) == 7 && t != SEQ_LEN - 1) {           // renormalize
            float* wq = &wbuf[1 - p][0];
            if (tid < 32) {
                float v = wq[tid] + ((tid < 16) ? wq[32 + tid] : 0.0f);
                #pragma unroll
                for (int off = 16; off; off >>= 1)
                    v += __shfl_xor_sync(0xffffffffu, v, off);
                if (tid == 0) sred = v;
            }
            __syncthreads();
            float s = sred;
            C += __logf(s);
            if (tid < NUM_TAGS) wbuf[1 - p][tid] *= (1.0f / s);
            __syncthreads();
        }
        p ^= 1;
    }

    // final partition: logZ = C + log(sum w)
    {
        float* wq = &wbuf[p][0];
        if (tid < 32) {
            float v = wq[tid] + ((tid < 16) ? wq[32 + tid] : 0.0f);
            #pragma unroll
            for (int off = 16; off; off >>= 1)
                v += __shfl_xor_sync(0xffffffffu, v, off);
            if (tid == 0) sred = v;
        }
        __syncthreads();
    }
    float logZ = C + __logf(sred);

    // ---------------- gold-path score ---------------------------------------
    float sc = 0.0f;
    for (int t = 1 + tid; t < SEQ_LEN; t += 64) {
        int tp = tags_b[t - 1], tc = tags_b[t];
        if (smask[t])
            sc += em_b[(size_t)t * NUM_TAGS + tc] + transitions[tp * NUM_TAGS + tc];
    }
    if (tid == 0) sc += em_b[tags_b[0]];

    rsh[tid] = sc;
    __syncthreads();
    #pragma unroll
    for (int s2 = 32; s2; s2 >>= 1) {
        if (tid < s2) rsh[tid] += rsh[tid + s2];
        __syncthreads();
    }

    if (tid == 0) g_nll[b] = logZ - rsh[0];
}

__global__ void crf_reduce_kernel(float* __restrict__ out)
{
    __shared__ float sh[256];
    int tid = threadIdx.x;
    float v = 0.0f;
    #pragma unroll
    for (int i = tid; i < BATCH; i += 256) v += g_nll[i];
    sh[tid] = v;
    __syncthreads();
    #pragma unroll
    for (int s = 128; s; s >>= 1) {
        if (tid < s) sh[tid] += sh[tid + s];
        __syncthreads();
    }
    if (tid == 0) out[0] = sh[0] * (1.0f / (float)BATCH);
}

extern "C" void kernel_launch(void* const* d_in, const int* in_sizes, int n_in,
                              void* d_out, int out_size)
{
    const float* emissions   = (const float*)d_in[0];
    const float* transitions = (const float*)d_in[1];
    const int*   tags        = (const int*)d_in[2];
    const int*   mask        = (const int*)d_in[3];
    float*       out         = (float*)d_out;

    crf_forward_kernel<<<BATCH, 64>>>(emissions, transitions, tags, mask);
    crf_reduce_kernel<<<1, 256>>>(out);
}

// round 2
// speedup vs baseline: 2.1522x; 2.1522x over previous
#include <cuda_runtime.h>
#include <cuda_bf16.h>
#include <cstdint>

#define NUM_TAGS 48
#define SEQ_LEN  512
#define BATCH    1024
#define CHUNK    8
#define NCHUNK   (SEQ_LEN / CHUNK)   // 64

__device__ float g_nll[BATCH];

// ---- packed f32x2 helpers (Blackwell FFMA2 path, PTX-only) ------------------
__device__ __forceinline__ void fma2(uint64_t& d, uint64_t a, uint64_t b) {
    asm("fma.rn.f32x2 %0, %1, %2, %0;" : "+l"(d) : "l"(a), "l"(b));
}
__device__ __forceinline__ uint64_t add2(uint64_t a, uint64_t b) {
    uint64_t d;
    asm("add.rn.f32x2 %0, %1, %2;" : "=l"(d) : "l"(a), "l"(b));
    return d;
}
__device__ __forceinline__ uint64_t pack2(float lo, float hi) {
    uint64_t d;
    asm("mov.b64 %0, {%1, %2};" : "=l"(d) : "f"(lo), "f"(hi));
    return d;
}
__device__ __forceinline__ float lo2(uint64_t v) { return __uint_as_float((uint32_t)v); }
__device__ __forceinline__ float hi2(uint64_t v) { return __uint_as_float((uint32_t)(v >> 32)); }

__device__ __forceinline__ void cp16(uint32_t saddr, const void* g) {
    asm volatile("cp.async.cg.shared.global [%0], [%1], 16;" :: "r"(saddr), "l"(g));
}

// One warp (one CTA) per batch element.
__global__ __launch_bounds__(32)
void crf_forward_kernel(const float* __restrict__ emissions,
                        const float* __restrict__ transitions,
                        const int*   __restrict__ tags,
                        const int*   __restrict__ mask)
{
    const int b    = blockIdx.x;
    const int lane = threadIdx.x;

    __shared__ __align__(16) float swbuf[2][NUM_TAGS];          // alpha ping-pong
    __shared__ __align__(16) float sem[2][CHUNK * NUM_TAGS];    // emission chunks
    __shared__ int smask[SEQ_LEN];
    __shared__ int stags[SEQ_LEN];

    const float* em_b   = emissions + (size_t)b * SEQ_LEN * NUM_TAGS;
    const int*   tags_b = tags + b * SEQ_LEN;
    const int*   mask_b = mask + b * SEQ_LEN;

    // --- stage emission chunk 0 (async, consumed after wait in main loop) ----
    {
        uint32_t dst = (uint32_t)__cvta_generic_to_shared(&sem[0][0]);
        #pragma unroll
        for (int r = 0; r < 3; r++)
            cp16(dst + lane * 16 + r * 512, em_b + lane * 4 + r * 128);
        asm volatile("cp.async.commit_group;");
    }

    // --- tags / mask to shared (vectorized) ----------------------------------
    #pragma unroll
    for (int r = 0; r < 4; r++) {
        ((int4*)stags)[lane + 32 * r] = ((const int4*)tags_b)[lane + 32 * r];
        ((int4*)smask)[lane + 32 * r] = ((const int4*)mask_b)[lane + 32 * r];
    }

    // --- E = exp(T): two adjacent columns per lane, packed over input pairs --
    const int j0 = 2 * (lane < 24 ? lane : 23);
    uint64_t E0[24], E1[24];
    #pragma unroll
    for (int k = 0; k < 24; k++) {
        E0[k] = pack2(__expf(transitions[(2 * k    ) * NUM_TAGS + j0]),
                      __expf(transitions[(2 * k + 1) * NUM_TAGS + j0]));
        E1[k] = pack2(__expf(transitions[(2 * k    ) * NUM_TAGS + j0 + 1]),
                      __expf(transitions[(2 * k + 1) * NUM_TAGS + j0 + 1]));
    }

    // --- init alphas (linear domain): only tag 0 live -------------------------
    float wa = (lane == 0) ? 1.0f : 0.0f;
    float wb = 0.0f;
    if (lane < 24) *(float2*)&swbuf[0][2 * lane] = make_float2(wa, wb);
    __syncwarp();

    // --- gold-path score (overlaps with staged chunk-0 latency) --------------
    float sc = 0.0f;
    #pragma unroll 4
    for (int t = 1 + lane; t < SEQ_LEN; t += 32) {
        int tc = stags[t], tp = stags[t - 1];
        if (smask[t])
            sc += em_b[(size_t)t * NUM_TAGS + tc] + transitions[tp * NUM_TAGS + tc];
    }
    #pragma unroll
    for (int off = 16; off; off >>= 1)
        sc += __shfl_xor_sync(0xffffffffu, sc, off);

    // --- forward recursion: 64 chunks x 8 steps -------------------------------
    float C = 0.0f;
    for (int c = 0; c < NCHUNK; c++) {
        if (c + 1 < NCHUNK) {
            uint32_t dst = (uint32_t)__cvta_generic_to_shared(&sem[(c + 1) & 1][0]);
            const float* src = em_b + (size_t)(c + 1) * CHUNK * NUM_TAGS;
            #pragma unroll
            for (int r = 0; r < 3; r++)
                cp16(dst + lane * 16 + r * 512, src + lane * 4 + r * 128);
        }
        asm volatile("cp.async.commit_group;");
        asm volatile("cp.async.wait_group 1;");
        __syncwarp();

        const float* eb = sem[c & 1];
        const int*   mb = smask + c * CHUNK;

        #pragma unroll
        for (int u = 0; u < CHUNK; u++) {
            // read buffer u&1, write buffer (u&1)^1 (p returns to 0 each chunk)
            const ulonglong2* wv = (const ulonglong2*)swbuf[u & 1];
            uint64_t a0 = 0, a1 = 0, b0 = 0, b1 = 0;
            #pragma unroll
            for (int i = 0; i < 12; i++) {
                ulonglong2 W = wv[i];
                fma2(a0, W.x, E0[2 * i]);
                fma2(a1, W.y, E0[2 * i + 1]);
                fma2(b0, W.x, E1[2 * i]);
                fma2(b1, W.y, E1[2 * i + 1]);
            }
            uint64_t s0 = add2(a0, a1);
            uint64_t s1 = add2(b0, b1);
            float d0 = lo2(s0) + hi2(s0);
            float d1 = lo2(s1) + hi2(s1);

            float2 e = *(const float2*)&eb[u * NUM_TAGS + j0];
            float na = d0 * __expf(e.x);
            float nb = d1 * __expf(e.y);

            int m = mb[u];
            wa = m ? na : wa;           // old alpha carried in registers
            wb = m ? nb : wb;

            if (lane < 24)
                *(float2*)&swbuf[(u & 1) ^ 1][2 * lane] = make_float2(wa, wb);
            __syncwarp();
        }

        // renormalize (also at the final chunk => logZ == C exactly)
        float v = (lane < 24) ? (wa + wb) : 0.0f;
        #pragma unroll
        for (int off = 16; off; off >>= 1)
            v += __shfl_xor_sync(0xffffffffu, v, off);
        C += __logf(v);
        float inv = 1.0f / v;
        wa *= inv;
        wb *= inv;
        if (lane < 24)
            *(float2*)&swbuf[0][2 * lane] = make_float2(wa, wb);
        __syncwarp();
    }

    if (lane == 0) {
        float score = sc + em_b[stags[0]];   // emit[0] always counted
        g_nll[b] = C - score;                // logZ == C after final renorm
    }
}

__global__ void crf_reduce_kernel(float* __restrict__ out)
{
    __shared__ float sh[256];
    int tid = threadIdx.x;
    float v = 0.0f;
    #pragma unroll
    for (int i = tid; i < BATCH; i += 256) v += g_nll[i];
    sh[tid] = v;
    __syncthreads();
    #pragma unroll
    for (int s = 128; s; s >>= 1) {
        if (tid < s) sh[tid] += sh[tid + s];
        __syncthreads();
    }
    if (tid == 0) out[0] = sh[0] * (1.0f / (float)BATCH);
}

extern "C" void kernel_launch(void* const* d_in, const int* in_sizes, int n_in,
                              void* d_out, int out_size)
{
    const float* emissions   = (const float*)d_in[0];
    const float* transitions = (const float*)d_in[1];
    const int*   tags        = (const int*)d_in[2];
    const int*   mask        = (const int*)d_in[3];
    float*       out         = (float*)d_out;

    crf_forward_kernel<<<BATCH, 32>>>(emissions, transitions, tags, mask);
    crf_reduce_kernel<<<1, 256>>>(out);
}

// round 3
// speedup vs baseline: 2.4309x; 1.1295x over previous
#include <cuda_runtime.h>
#include <cuda_bf16.h>
#include <cstdint>

#define NUM_TAGS 48
#define SEQ_LEN  512
#define BATCH    1024
#define CHUNK    8
#define NCHUNK   (SEQ_LEN / CHUNK)   // 64

__device__ float    g_nll[BATCH];
__device__ unsigned g_count = 0;

// ---- packed f32x2 helpers (Blackwell FFMA2 path, PTX-only) ------------------
__device__ __forceinline__ void fma2(uint64_t& d, uint64_t a, uint64_t b) {
    asm("fma.rn.f32x2 %0, %1, %2, %0;" : "+l"(d) : "l"(a), "l"(b));
}
__device__ __forceinline__ uint64_t add2(uint64_t a, uint64_t b) {
    uint64_t d;
    asm("add.rn.f32x2 %0, %1, %2;" : "=l"(d) : "l"(a), "l"(b));
    return d;
}
__device__ __forceinline__ uint64_t pack2(float lo, float hi) {
    uint64_t d;
    asm("mov.b64 %0, {%1, %2};" : "=l"(d) : "f"(lo), "f"(hi));
    return d;
}
__device__ __forceinline__ float lo2(uint64_t v) { return __uint_as_float((uint32_t)v); }
__device__ __forceinline__ float hi2(uint64_t v) { return __uint_as_float((uint32_t)(v >> 32)); }

__device__ __forceinline__ void cp16(uint32_t saddr, const void* g) {
    asm volatile("cp.async.cg.shared.global [%0], [%1], 16;" :: "r"(saddr), "l"(g));
}

// One warp (one CTA) per batch element; fused final reduction in the last CTA.
__global__ __launch_bounds__(32)
void crf_fused_kernel(const float* __restrict__ emissions,
                      const float* __restrict__ transitions,
                      const int*   __restrict__ tags,
                      const int*   __restrict__ mask,
                      float*       __restrict__ out)
{
    const int b    = blockIdx.x;
    const int lane = threadIdx.x;
    const int h    = lane >> 4;     // input half: i in [24h, 24h+24)
    const int q    = lane & 15;     // output triple: j in {3q, 3q+1, 3q+2}
    const int j0   = 3 * q;
    const int i0   = 24 * h;

    __shared__ __align__(16) float swbuf[2][NUM_TAGS];        // alpha ping-pong
    __shared__ __align__(16) float sem[2][CHUNK * NUM_TAGS];  // emission chunks
    __shared__ int smask[SEQ_LEN];
    __shared__ int stags[SEQ_LEN];

    const float* em_b   = emissions + (size_t)b * SEQ_LEN * NUM_TAGS;
    const int*   tags_b = tags + b * SEQ_LEN;
    const int*   mask_b = mask + b * SEQ_LEN;

    // --- stage emission chunk 0 ----------------------------------------------
    {
        uint32_t dst = (uint32_t)__cvta_generic_to_shared(&sem[0][0]);
        #pragma unroll
        for (int r = 0; r < 3; r++)
            cp16(dst + lane * 16 + r * 512, em_b + lane * 4 + r * 128);
        asm volatile("cp.async.commit_group;");
    }

    // --- tags / mask to shared (vectorized) ----------------------------------
    #pragma unroll
    for (int r = 0; r < 4; r++) {
        ((int4*)stags)[lane + 32 * r] = ((const int4*)tags_b)[lane + 32 * r];
        ((int4*)smask)[lane + 32 * r] = ((const int4*)mask_b)[lane + 32 * r];
    }

    // --- E = exp(T): half-column slices, 3 output cols per lane ---------------
    // Ec[c*12+k] = (exp T[i0+2k][j0+c], exp T[i0+2k+1][j0+c])
    uint64_t Ec[36];
    #pragma unroll
    for (int c = 0; c < 3; c++)
        #pragma unroll
        for (int k = 0; k < 12; k++)
            Ec[c * 12 + k] = pack2(__expf(transitions[(i0 + 2 * k    ) * NUM_TAGS + j0 + c]),
                                   __expf(transitions[(i0 + 2 * k + 1) * NUM_TAGS + j0 + c]));

    // --- init alphas (linear domain): only tag 0 live --------------------------
    float w0 = (q == 0) ? 1.0f : 0.0f;   // j0 == 0 only for q == 0
    float w1 = 0.0f, w2 = 0.0f;
    if (h == 0) {
        swbuf[0][j0]     = w0;
        swbuf[0][j0 + 1] = w1;
        swbuf[0][j0 + 2] = w2;
    }
    __syncwarp();

    // --- gold-path score (overlaps staged chunk-0 latency) --------------------
    float sc = 0.0f;
    #pragma unroll 4
    for (int t = 1 + lane; t < SEQ_LEN; t += 32) {
        int tc = stags[t], tp = stags[t - 1];
        if (smask[t])
            sc += em_b[(size_t)t * NUM_TAGS + tc] + transitions[tp * NUM_TAGS + tc];
    }
    #pragma unroll
    for (int off = 16; off; off >>= 1)
        sc += __shfl_xor_sync(0xffffffffu, sc, off);

    // --- forward recursion: 64 chunks x 8 steps --------------------------------
    float C = 0.0f;
    for (int c = 0; c < NCHUNK; c++) {
        if (c + 1 < NCHUNK) {
            uint32_t dst = (uint32_t)__cvta_generic_to_shared(&sem[(c + 1) & 1][0]);
            const float* src = em_b + (size_t)(c + 1) * CHUNK * NUM_TAGS;
            #pragma unroll
            for (int r = 0; r < 3; r++)
                cp16(dst + lane * 16 + r * 512, src + lane * 4 + r * 128);
        }
        asm volatile("cp.async.commit_group;");
        asm volatile("cp.async.wait_group 1;");
        __syncwarp();

        const float* eb = sem[c & 1];
        const int*   mb = smask + c * CHUNK;

        // hoist all emission exps for this chunk off the recurrence chain
        float eE[CHUNK][3];
        #pragma unroll
        for (int u = 0; u < CHUNK; u++) {
            eE[u][0] = __expf(eb[u * NUM_TAGS + j0]);
            eE[u][1] = __expf(eb[u * NUM_TAGS + j0 + 1]);
            eE[u][2] = __expf(eb[u * NUM_TAGS + j0 + 2]);
        }

        #pragma unroll
        for (int u = 0; u < CHUNK; u++) {
            const ulonglong2* wv = (const ulonglong2*)(swbuf[u & 1] + i0);
            uint64_t a0[3] = {0, 0, 0}, a1[3] = {0, 0, 0};
            #pragma unroll
            for (int r = 0; r < 6; r++) {
                ulonglong2 W = wv[r];
                #pragma unroll
                for (int cc = 0; cc < 3; cc++) {
                    fma2(a0[cc], W.x, Ec[cc * 12 + 2 * r]);
                    fma2(a1[cc], W.y, Ec[cc * 12 + 2 * r + 1]);
                }
            }
            int m = mb[u];
            float nv[3];
            #pragma unroll
            for (int cc = 0; cc < 3; cc++) {
                uint64_t s = add2(a0[cc], a1[cc]);
                float d = lo2(s) + hi2(s);                  // half-dot
                d += __shfl_xor_sync(0xffffffffu, d, 16);   // combine halves
                nv[cc] = d * eE[u][cc];
            }
            w0 = m ? nv[0] : w0;
            w1 = m ? nv[1] : w1;
            w2 = m ? nv[2] : w2;
            if (h == 0) {
                float* wd = swbuf[(u & 1) ^ 1];
                wd[j0]     = w0;
                wd[j0 + 1] = w1;
                wd[j0 + 2] = w2;
            }
            __syncwarp();
        }

        // renormalize (also at the final chunk => logZ == C exactly)
        float v = (h == 0) ? (w0 + w1 + w2) : 0.0f;
        #pragma unroll
        for (int off = 16; off; off >>= 1)
            v += __shfl_xor_sync(0xffffffffu, v, off);
        C += __logf(v);
        float inv = 1.0f / v;
        w0 *= inv; w1 *= inv; w2 *= inv;
        if (h == 0) {
            swbuf[0][j0]     = w0;
            swbuf[0][j0 + 1] = w1;
            swbuf[0][j0 + 2] = w2;
        }
        __syncwarp();
    }

    if (lane == 0) {
        float score = sc + em_b[stags[0]];   // emit[0] always counted
        g_nll[b] = C - score;                // logZ == C after final renorm
    }

    // --- fused mean-reduce: last CTA to finish does the deterministic sum ------
    unsigned done = 0;
    if (lane == 0) {
        __threadfence();
        done = atomicAdd(&g_count, 1u);
    }
    done = __shfl_sync(0xffffffffu, done, 0);
    if (done == BATCH - 1) {
        __threadfence();
        float v = 0.0f;
        #pragma unroll
        for (int i = lane; i < BATCH; i += 32)
            v += __ldcg(&g_nll[i]);
        #pragma unroll
        for (int off = 16; off; off >>= 1)
            v += __shfl_xor_sync(0xffffffffu, v, off);
        if (lane == 0) {
            out[0] = v * (1.0f / (float)BATCH);
            g_count = 0;   // reset for next graph replay
        }
    }
}

extern "C" void kernel_launch(void* const* d_in, const int* in_sizes, int n_in,
                              void* d_out, int out_size)
{
    const float* emissions   = (const float*)d_in[0];
    const float* transitions = (const float*)d_in[1];
    const int*   tags        = (const int*)d_in[2];
    const int*   mask        = (const int*)d_in[3];
    float*       out         = (float*)d_out;

    crf_fused_kernel<<<BATCH, 32>>>(emissions, transitions, tags, mask, out);
}